// round 10
// baseline (speedup 1.0000x reference)
#include <cuda_runtime.h>
#include <math.h>

#define N_EDGES_C   1600000

__device__ __constant__ float kPiOverCutoff = 0.5235987755982988f;   // pi/6
__device__ __constant__ float kCutoff       = 6.0f;

__global__ __launch_bounds__(256)
void edge_feature_kernel(const float* __restrict__ pos,
                         const int* __restrict__ edge_index,
                         float* __restrict__ out,
                         // exp-normal RBF constants (host-computed in double)
                         float cAlpha,   // 5/6
                         float cStart,   // exp(-6)
                         float cDelta,   // (1-exp(-6))/127
                         float cBeta,    // ((2/128)(1-exp(-6)))^-2
                         float cTwoBD,   // 2*beta*delta
                         float cNegBD2,  // -beta*delta^2
                         float cQE,      // exp(-2*beta*delta^2)
                         // gaussian constants
                         float cGDelta,  // 10/31
                         float cGInv,    // 20.48
                         float cTwoGD,   // 2*gInv*gDelta
                         float cNegGD2,  // -gInv*gDelta^2
                         float cQG)      // exp(-2*gInv*gDelta^2)
{
    const int t    = threadIdx.x;
    const int lane = t & 31;
    const int warp = t >> 5;

    // First edge owned by this warp (32 edges per warp, 8 warps per block)
    const long long wbase = (long long)blockIdx.x * 256 + warp * 32;

    // ---------------- Phase 1: per-edge scalars, one edge per lane (registers,
    // no smem, no block barrier — warps fully independent) --------------------
    float r_d, r_c, r_e;
    {
        const long long e = wbase + lane;
        const int s = edge_index[e];
        const int d = edge_index[N_EDGES_C + e];

        const float sx = __ldg(&pos[3 * s + 0]);
        const float sy = __ldg(&pos[3 * s + 1]);
        const float sz = __ldg(&pos[3 * s + 2]);
        const float dx = sx - __ldg(&pos[3 * d + 0]);
        const float dy = sy - __ldg(&pos[3 * d + 1]);
        const float dz = sz - __ldg(&pos[3 * d + 2]);

        const float dist = sqrtf(fmaf(dx, dx, fmaf(dy, dy, fmaf(dz, dz, 1e-12f))));
        float c = 0.5f * (cosf(dist * kPiOverCutoff) + 1.0f);
        c = (dist < kCutoff) ? c : 0.0f;

        r_d = dist;
        r_c = c;
        r_e = expf(-cAlpha * dist);   // accurate: error amplified by 2*beta*u
    }

    // ---------------- Phase 2: 8 threads per edge, 4 edges per warp-tile -----
    const int sub  = lane & 7;     // float4 column set this thread owns
    const int erow = lane >> 3;    // edge-within-tile (0..3)

    const float fsub = (float)sub;
    // exp-normal means at feature index 4*(sub+8j): m_j = start + (4*sub+32j)*delta
    const float m0 = fmaf(fsub, 4.0f * cDelta, cStart);
    const float m1 = fmaf(32.0f, cDelta, m0);
    const float m2 = fmaf(64.0f, cDelta, m0);
    const float m3 = fmaf(96.0f, cDelta, m0);
    // gaussian center at feature 4*sub
    const float gc0 = fsub * (4.0f * cGDelta);

    float4* __restrict__ o4 = reinterpret_cast<float4*>(out)
                              + (wbase + erow) * 40 + sub;

    #pragma unroll 1
    for (int tile = 0; tile < 8; ++tile) {
        const int src = tile * 4 + erow;   // lane holding this edge's scalars
        const float dist = __shfl_sync(0xffffffffu, r_d, src);
        const float cut  = __shfl_sync(0xffffffffu, r_c, src);
        const float ex   = __shfl_sync(0xffffffffu, r_e, src);

        // j = 0..3 : exp-normal groups (f4 = sub + 8j), geometric 4-chain
        {
            float u, f0, r;
            float4 v;

            u  = ex - m0;
            f0 = cut * __expf(-cBeta * (u * u));
            r  = __expf(fmaf(cTwoBD, u, cNegBD2));
            v.x = f0; v.y = f0 * r; r *= cQE; v.z = v.y * r; r *= cQE; v.w = v.z * r;
            o4[0] = v;

            u  = ex - m1;
            f0 = cut * __expf(-cBeta * (u * u));
            r  = __expf(fmaf(cTwoBD, u, cNegBD2));
            v.x = f0; v.y = f0 * r; r *= cQE; v.z = v.y * r; r *= cQE; v.w = v.z * r;
            o4[8] = v;

            u  = ex - m2;
            f0 = cut * __expf(-cBeta * (u * u));
            r  = __expf(fmaf(cTwoBD, u, cNegBD2));
            v.x = f0; v.y = f0 * r; r *= cQE; v.z = v.y * r; r *= cQE; v.w = v.z * r;
            o4[16] = v;

            u  = ex - m3;
            f0 = cut * __expf(-cBeta * (u * u));
            r  = __expf(fmaf(cTwoBD, u, cNegBD2));
            v.x = f0; v.y = f0 * r; r *= cQE; v.z = v.y * r; r *= cQE; v.w = v.z * r;
            o4[24] = v;
        }

        // j = 4 : gaussian group (f4 = 32 + sub), centers (4*sub + i)*gDelta
        {
            const float u  = dist - gc0;
            const float f0 = __expf(-cGInv * (u * u));
            // ratio arg can reach ~130 for large dist -> clamp (exact: the
            // whole group is a true zero whenever the clamp engages)
            float a = fmaf(cTwoGD, u, cNegGD2);
            a = fminf(a, 85.0f);
            float r = __expf(a);
            float4 v;
            v.x = f0; v.y = f0 * r; r *= cQG; v.z = v.y * r; r *= cQG; v.w = v.z * r;
            o4[32] = v;
        }

        o4 += 4 * 40;   // next 4 edges
    }
}

extern "C" void kernel_launch(void* const* d_in, const int* in_sizes, int n_in,
                              void* d_out, int out_size)
{
    const float* pos = (const float*)d_in[0];
    const int*   ei  = (const int*)d_in[1];
    float*       out = (float*)d_out;

    // Host-side double-precision constant computation
    const double cutoff = 6.0;
    const double alpha  = 5.0 / cutoff;
    const double start  = exp(-cutoff);
    const double delta  = (1.0 - start) / 127.0;           // NUM_RBF-1
    const double betaD  = pow((2.0 / 128.0) * (1.0 - start), -2.0);
    const double twoBD  = 2.0 * betaD * delta;
    const double negBD2 = -betaD * delta * delta;
    const double qE     = exp(-2.0 * betaD * delta * delta);

    const double gDelta = 10.0 / 31.0;                      // GAUSS span / (NB-1)
    const double gW     = 0.5 * 10.0 / 32.0;                // width
    const double gInv   = 1.0 / (2.0 * gW * gW);            // 20.48
    const double twoGD  = 2.0 * gInv * gDelta;
    const double negGD2 = -gInv * gDelta * gDelta;
    const double qG     = exp(-2.0 * gInv * gDelta * gDelta);

    // 1,600,000 edges / 256 per block = 6250 blocks exactly
    edge_feature_kernel<<<N_EDGES_C / 256, 256>>>(
        pos, ei, out,
        (float)alpha, (float)start, (float)delta, (float)betaD,
        (float)twoBD, (float)negBD2, (float)qE,
        (float)gDelta, (float)gInv, (float)twoGD, (float)negGD2, (float)qG);
}

// round 12
// speedup vs baseline: 1.0826x; 1.0826x over previous
#include <cuda_runtime.h>
#include <math.h>

#define N_EDGES_C   1600000

__device__ __constant__ float kPiOverCutoff = 0.5235987755982988f;   // pi/6
__device__ __constant__ float kCutoff       = 6.0f;

__global__ __launch_bounds__(256)
void edge_feature_kernel(const float* __restrict__ pos,
                         const int* __restrict__ edge_index,
                         float* __restrict__ out,
                         // exp-normal RBF constants (host-computed in double)
                         float cAlpha,   // 5/6
                         float cStart,   // exp(-6)
                         float cDelta,   // (1-exp(-6))/127
                         float cBeta,    // ((2/128)(1-exp(-6)))^-2
                         float cTwoBD,   // 2*beta*delta
                         float cNegBD2,  // -beta*delta^2
                         float cQE,      // exp(-2*beta*delta^2)
                         // gaussian constants
                         float cGDelta,  // 10/31
                         float cGInv,    // 20.48
                         float cTwoGD,   // 2*gInv*gDelta
                         float cNegGD2,  // -gInv*gDelta^2
                         float cQG)      // exp(-2*gInv*gDelta^2)
{
    const int t    = threadIdx.x;
    const int lane = t & 31;
    const int warp = t >> 5;

    // First edge owned by this warp (32 edges per warp, 8 warps per block)
    const long long wbase = (long long)blockIdx.x * 256 + warp * 32;

    // ---------------- Phase 1: per-edge scalars, one edge per lane (registers,
    // no smem, no block barrier — warps fully independent) --------------------
    float r_d, r_c, r_e;
    {
        const long long e = wbase + lane;
        const int s = edge_index[e];
        const int d = edge_index[N_EDGES_C + e];

        const float sx = __ldg(&pos[3 * s + 0]);
        const float sy = __ldg(&pos[3 * s + 1]);
        const float sz = __ldg(&pos[3 * s + 2]);
        const float dx = sx - __ldg(&pos[3 * d + 0]);
        const float dy = sy - __ldg(&pos[3 * d + 1]);
        const float dz = sz - __ldg(&pos[3 * d + 2]);

        const float dist = sqrtf(fmaf(dx, dx, fmaf(dy, dy, fmaf(dz, dz, 1e-12f))));
        float c = 0.5f * (cosf(dist * kPiOverCutoff) + 1.0f);
        c = (dist < kCutoff) ? c : 0.0f;

        r_d = dist;
        r_c = c;
        r_e = expf(-cAlpha * dist);   // accurate: error amplified by 2*beta*u
    }

    // ---------------- Phase 2: 8 threads per edge, 4 edges per warp-tile -----
    const int sub  = lane & 7;     // float4 column set this thread owns
    const int erow = lane >> 3;    // edge-within-tile (0..3)

    const float fsub = (float)sub;
    // exp-normal means at feature index 4*(sub+8j): m_j = start + (4*sub+32j)*delta
    const float m0 = fmaf(fsub, 4.0f * cDelta, cStart);
    const float m1 = fmaf(32.0f, cDelta, m0);
    const float m2 = fmaf(64.0f, cDelta, m0);
    const float m3 = fmaf(96.0f, cDelta, m0);
    // gaussian center at feature 4*sub
    const float gc0 = fsub * (4.0f * cGDelta);

    float4* __restrict__ o4 = reinterpret_cast<float4*>(out)
                              + (wbase + erow) * 40 + sub;

    #pragma unroll 1
    for (int tile = 0; tile < 8; ++tile) {
        const int src = tile * 4 + erow;   // lane holding this edge's scalars
        const float dist = __shfl_sync(0xffffffffu, r_d, src);
        const float cut  = __shfl_sync(0xffffffffu, r_c, src);
        const float ex   = __shfl_sync(0xffffffffu, r_e, src);

        // j = 0..3 : exp-normal groups (f4 = sub + 8j), geometric 4-chain
        {
            float u, f0, r;
            float4 v;

            u  = ex - m0;
            f0 = cut * __expf(-cBeta * (u * u));
            r  = __expf(fmaf(cTwoBD, u, cNegBD2));
            v.x = f0; v.y = f0 * r; r *= cQE; v.z = v.y * r; r *= cQE; v.w = v.z * r;
            __stcs(&o4[0], v);

            u  = ex - m1;
            f0 = cut * __expf(-cBeta * (u * u));
            r  = __expf(fmaf(cTwoBD, u, cNegBD2));
            v.x = f0; v.y = f0 * r; r *= cQE; v.z = v.y * r; r *= cQE; v.w = v.z * r;
            __stcs(&o4[8], v);

            u  = ex - m2;
            f0 = cut * __expf(-cBeta * (u * u));
            r  = __expf(fmaf(cTwoBD, u, cNegBD2));
            v.x = f0; v.y = f0 * r; r *= cQE; v.z = v.y * r; r *= cQE; v.w = v.z * r;
            __stcs(&o4[16], v);

            u  = ex - m3;
            f0 = cut * __expf(-cBeta * (u * u));
            r  = __expf(fmaf(cTwoBD, u, cNegBD2));
            v.x = f0; v.y = f0 * r; r *= cQE; v.z = v.y * r; r *= cQE; v.w = v.z * r;
            __stcs(&o4[24], v);
        }

        // j = 4 : gaussian group (f4 = 32 + sub), centers (4*sub + i)*gDelta
        {
            const float u  = dist - gc0;
            const float f0 = __expf(-cGInv * (u * u));
            // ratio arg can reach ~130 for large dist -> clamp (exact: the
            // whole group is a true zero whenever the clamp engages)
            float a = fmaf(cTwoGD, u, cNegGD2);
            a = fminf(a, 85.0f);
            float r = __expf(a);
            float4 v;
            v.x = f0; v.y = f0 * r; r *= cQG; v.z = v.y * r; r *= cQG; v.w = v.z * r;
            __stcs(&o4[32], v);
        }

        o4 += 4 * 40;   // next 4 edges
    }
}

extern "C" void kernel_launch(void* const* d_in, const int* in_sizes, int n_in,
                              void* d_out, int out_size)
{
    const float* pos = (const float*)d_in[0];
    const int*   ei  = (const int*)d_in[1];
    float*       out = (float*)d_out;

    // Host-side double-precision constant computation
    const double cutoff = 6.0;
    const double alpha  = 5.0 / cutoff;
    const double start  = exp(-cutoff);
    const double delta  = (1.0 - start) / 127.0;           // NUM_RBF-1
    const double betaD  = pow((2.0 / 128.0) * (1.0 - start), -2.0);
    const double twoBD  = 2.0 * betaD * delta;
    const double negBD2 = -betaD * delta * delta;
    const double qE     = exp(-2.0 * betaD * delta * delta);

    const double gDelta = 10.0 / 31.0;                      // GAUSS span / (NB-1)
    const double gW     = 0.5 * 10.0 / 32.0;                // width
    const double gInv   = 1.0 / (2.0 * gW * gW);            // 20.48
    const double twoGD  = 2.0 * gInv * gDelta;
    const double negGD2 = -gInv * gDelta * gDelta;
    const double qG     = exp(-2.0 * gInv * gDelta * gDelta);

    // 1,600,000 edges / 256 per block = 6250 blocks exactly
    edge_feature_kernel<<<N_EDGES_C / 256, 256>>>(
        pos, ei, out,
        (float)alpha, (float)start, (float)delta, (float)betaD,
        (float)twoBD, (float)negBD2, (float)qE,
        (float)gDelta, (float)gInv, (float)twoGD, (float)negGD2, (float)qG);
}